// round 7
// baseline (speedup 1.0000x reference)
#include <cuda_runtime.h>
#include <cstdint>

#define BB 4
#define CC 512
#define KK 64
#define NN 1024
#define GRID 128
#define NTB 32   // phase B n-tile

typedef unsigned long long ull;

// ---- scratch (static __device__, no allocations) ----
__device__ __align__(16) float g_inv[KK * CC];    // [k][c]
__device__ __align__(16) float g_inv2t[CC * KK];  // [c][k]
__device__ __align__(16) float g_m2t[CC * KK];    // [c][k]
__device__ __align__(16) float g_ck[KK];
__device__ __align__(16) float g_wpart[(NN / NTB) * BB * KK];  // [(b*32+nb)*KK+k]
__device__ __align__(16) float g_part[4 * BB * KK * CC];
__device__ unsigned g_bar_count = 0;
__device__ unsigned g_bar_gen = 0;

// ---- f32x2 helpers ----
__device__ __forceinline__ ull pack2(float x, float y) {
    ull r; asm("mov.b64 %0, {%1,%2};" : "=l"(r) : "f"(x), "f"(y)); return r;
}
__device__ __forceinline__ ull fma2(ull a, ull b, ull c) {
    ull d; asm("fma.rn.f32x2 %0, %1, %2, %3;" : "=l"(d) : "l"(a), "l"(b), "l"(c)); return d;
}
__device__ __forceinline__ float2 unpack2(ull v) {
    float2 f; asm("mov.b64 {%0,%1}, %2;" : "=f"(f.x), "=f"(f.y) : "l"(v)); return f;
}

// ---- cp.async helpers ----
__device__ __forceinline__ void cp_async16(void* smem_dst, const void* gsrc) {
    unsigned sa = (unsigned)__cvta_generic_to_shared(smem_dst);
    asm volatile("cp.async.cg.shared.global [%0], [%1], 16;\n" :: "r"(sa), "l"(gsrc));
}
__device__ __forceinline__ void cp_commit() { asm volatile("cp.async.commit_group;\n"); }
template <int N>
__device__ __forceinline__ void cp_wait() { asm volatile("cp.async.wait_group %0;\n" :: "n"(N)); }

// ---- grid-wide sense-reversing barrier (all GRID blocks resident) ----
__device__ __forceinline__ void grid_bar() {
    __threadfence();
    __syncthreads();
    if (threadIdx.x == 0) {
        unsigned gen = *(volatile unsigned*)&g_bar_gen;
        if (atomicAdd(&g_bar_count, 1u) == GRID - 1) {
            g_bar_count = 0;
            __threadfence();
            *(volatile unsigned*)&g_bar_gen = gen + 1;
        } else {
            while (*(volatile unsigned*)&g_bar_gen == gen) { __nanosleep(32); }
        }
        __threadfence();
    }
    __syncthreads();
}

// ------------------------------------------------------------------
// One fused kernel: prep -> d2+softmax -> num GEMM -> epilogue
// ------------------------------------------------------------------
__global__ __launch_bounds__(256) void fused_all(const float* __restrict__ x,
                                                 const float* __restrict__ anchor,
                                                 const float* __restrict__ sp,
                                                 float* __restrict__ nodes_out,
                                                 float* __restrict__ soft_out) {
    __shared__ __align__(16) unsigned char SMEM[31232];
    const int tid = threadIdx.x;
    const int blk = blockIdx.x;

    // ========== Phase A: prep (blocks 0..15, 4 k-rows each) ==========
    if (blk < 16) {
        float* smI2 = (float*)SMEM;                 // 4*512
        float* smM2 = smI2 + 4 * 512;               // 4*512
        float* ckred = smM2 + 4 * 512;              // 8*4
        const int k0 = blk * 4;
        const int lane = tid & 31, wid = tid >> 5;
        float ck4[4] = {0.f, 0.f, 0.f, 0.f};
#pragma unroll
        for (int kl = 0; kl < 4; kl++) {
#pragma unroll
            for (int h = 0; h < 2; h++) {
                const int c = tid + h * 256;
                const int gi = (k0 + kl) * CC + c;
                const float s = 1.f / (1.f + __expf(-sp[gi]));
                const float inv = __fdividef(1.f, s + 1e-7f);
                const float inv2 = inv * inv;
                const float a = anchor[gi];
                g_inv[gi] = inv;
                smI2[kl * 512 + c] = inv2;
                smM2[kl * 512 + c] = -2.f * a * inv2;
                ck4[kl] += a * a * inv2;
            }
        }
#pragma unroll
        for (int kl = 0; kl < 4; kl++) {
            float v = ck4[kl];
#pragma unroll
            for (int o = 16; o > 0; o >>= 1) v += __shfl_xor_sync(0xffffffffu, v, o);
            if (lane == 0) ckred[wid * 4 + kl] = v;
        }
        __syncthreads();
        if (tid < 4) {
            float s = 0.f;
#pragma unroll
            for (int w = 0; w < 8; w++) s += ckred[w * 4 + tid];
            g_ck[k0 + tid] = s;
        }
#pragma unroll
        for (int h = 0; h < 2; h++) {
            const int c = tid + h * 256;
            float4 v = make_float4(smI2[c], smI2[512 + c], smI2[1024 + c], smI2[1536 + c]);
            *reinterpret_cast<float4*>(&g_inv2t[c * KK + k0]) = v;
            float4 v2 = make_float4(smM2[c], smM2[512 + c], smM2[1024 + c], smM2[1536 + c]);
            *reinterpret_cast<float4*>(&g_m2t[c * KK + k0]) = v2;
        }
    }
    grid_bar();

    // ========== Phase B: d2 GEMM (64k x 32n) + softmax, 128 items ==========
    {
        float* Wis = (float*)SMEM;          // 2*1024
        float* M2s = Wis + 2048;            // 2*1024
        float* Xs = M2s + 2048;             // 2*512
        float* S = Xs + 1024;               // 64*33
        float* pm = S + 2112;               // 256
        float* ps = pm + 256;               // 256
        const int b = blk & 3;
        const int nb = blk >> 2;            // 0..31
        const int n0 = nb * NTB;
        const int tk = tid >> 4;            // 0..15 -> k base tk*4
        const int tn = tid & 15;            // 0..15 -> n base tn*2
        const float* xb = x + (size_t)b * CC * NN;

        auto issueB = [&](int chunk, int buf) {
            const int c0 = chunk * 16;
            cp_async16(&Wis[buf * 1024 + tid * 4], g_inv2t + c0 * KK + tid * 4);
            cp_async16(&M2s[buf * 1024 + tid * 4], g_m2t + c0 * KK + tid * 4);
            if (tid < 128) {
                const int cc = tid >> 3, nn4 = (tid & 7) * 4;
                cp_async16(&Xs[buf * 512 + cc * NTB + nn4],
                           xb + (size_t)(c0 + cc) * NN + n0 + nn4);
            }
            cp_commit();
        };

        ull acc[2][2];
#pragma unroll
        for (int i = 0; i < 2; i++)
#pragma unroll
            for (int j = 0; j < 2; j++) acc[i][j] = 0ull;

        issueB(0, 0);
        for (int ch = 0; ch < 32; ch++) {
            if (ch + 1 < 32) { issueB(ch + 1, (ch + 1) & 1); cp_wait<1>(); }
            else             { cp_wait<0>(); }
            __syncthreads();
            const float* Wb = Wis + (ch & 1) * 1024;
            const float* Mb = M2s + (ch & 1) * 1024;
            const float* Xb = Xs + (ch & 1) * 512;
#pragma unroll
            for (int cc = 0; cc < 16; cc++) {
                const ulonglong2 wp = *reinterpret_cast<const ulonglong2*>(Wb + cc * 64 + tk * 4);
                const ulonglong2 mp = *reinterpret_cast<const ulonglong2*>(Mb + cc * 64 + tk * 4);
                const float2 xv = *reinterpret_cast<const float2*>(Xb + cc * NTB + tn * 2);
                const ull xd0 = pack2(xv.x, xv.x);
                const ull xd1 = pack2(xv.y, xv.y);
                ull t;
                t = fma2(wp.x, xd0, mp.x); acc[0][0] = fma2(t, xd0, acc[0][0]);
                t = fma2(wp.x, xd1, mp.x); acc[0][1] = fma2(t, xd1, acc[0][1]);
                t = fma2(wp.y, xd0, mp.y); acc[1][0] = fma2(t, xd0, acc[1][0]);
                t = fma2(wp.y, xd1, mp.y); acc[1][1] = fma2(t, xd1, acc[1][1]);
            }
            __syncthreads();
        }

        // logits -> S (stride 33)
        {
            const int k0 = tk * 4;
#pragma unroll
            for (int kp = 0; kp < 2; kp++)
#pragma unroll
                for (int j = 0; j < 2; j++) {
                    const float2 v = unpack2(acc[kp][j]);
                    const int kk = k0 + kp * 2;
                    const int n = tn * 2 + j;
                    S[kk * 33 + n] = -0.5f * (v.x + g_ck[kk]);
                    S[(kk + 1) * 33 + n] = -0.5f * (v.y + g_ck[kk + 1]);
                }
        }
        __syncthreads();

        // parallel softmax: kg = tid>>5 owns 8 k, column n = tid&31
        {
            const int n = tid & 31;
            const int kg = tid >> 5;  // 0..7
            const int kb = kg * 8;
            float v[8];
#pragma unroll
            for (int i = 0; i < 8; i++) v[i] = S[(kb + i) * 33 + n];
            float m8 = v[0];
#pragma unroll
            for (int i = 1; i < 8; i++) m8 = fmaxf(m8, v[i]);
            pm[kg * 32 + n] = m8;
            __syncthreads();
            float m = pm[n];
#pragma unroll
            for (int j = 1; j < 8; j++) m = fmaxf(m, pm[j * 32 + n]);
            float e[8];
            float es = 0.f;
#pragma unroll
            for (int i = 0; i < 8; i++) { e[i] = __expf(v[i] - m); es += e[i]; }
            ps[kg * 32 + n] = es;
            __syncthreads();
            float s = ps[n];
#pragma unroll
            for (int j = 1; j < 8; j++) s += ps[j * 32 + n];
            const float invs = 1.f / s;
            float* outp = soft_out + (size_t)b * KK * NN + n0 + n;
#pragma unroll
            for (int i = 0; i < 8; i++) {
                const float p = e[i] * invs;
                S[(kb + i) * 33 + n] = p;
                outp[(size_t)(kb + i) * NN] = p;
            }
        }
        __syncthreads();

        // per-item wsum partials
        if (tid < 64) {
            float s = 0.f;
#pragma unroll
            for (int n = 0; n < NTB; n++) s += S[tid * 33 + n];
            g_wpart[(b * 32 + nb) * KK + tid] = s;
        }
    }
    grid_bar();

    // ========== Phase C: num GEMM, 128 items (8c x 4b x 4 n-splits) ==========
    {
        float* As = (float*)SMEM;         // 16*68
        float* Xs = As + 16 * 68;         // 16*68
        const int ct = blk & 7;
        const int b = (blk >> 3) & 3;
        const int ns = blk >> 5;          // 0..3
        const int c0 = ct * 64;
        const int nbeg = ns * (NN / 4);
        const int tc = tid & 15;
        const int tk = tid >> 4;

        ull acc2[4][2];
#pragma unroll
        for (int i = 0; i < 4; i++) { acc2[i][0] = 0ull; acc2[i][1] = 0ull; }

        const float* Ab = soft_out + (size_t)b * KK * NN;
        const float* xb = x + (size_t)b * CC * NN;

        for (int n0 = nbeg; n0 < nbeg + NN / 4; n0 += 16) {
#pragma unroll
            for (int r = 0; r < 4; r++) {
                const int idx = tid + r * 256;
                const int row = idx >> 4;
                const int nn = idx & 15;
                As[nn * 68 + row] = Ab[(size_t)row * NN + n0 + nn];
                Xs[nn * 68 + row] = xb[(size_t)(c0 + row) * NN + n0 + nn];
            }
            __syncthreads();
#pragma unroll
            for (int nn = 0; nn < 16; nn++) {
                const float4 a4 = *reinterpret_cast<const float4*>(&As[nn * 68 + tk * 4]);
                const ull ad0 = pack2(a4.x, a4.x);
                const ull ad1 = pack2(a4.y, a4.y);
                const ull ad2 = pack2(a4.z, a4.z);
                const ull ad3 = pack2(a4.w, a4.w);
                const float4 x4 = *reinterpret_cast<const float4*>(&Xs[nn * 68 + tc * 4]);
                const ull xq0 = pack2(x4.x, x4.y);
                const ull xq1 = pack2(x4.z, x4.w);
                acc2[0][0] = fma2(ad0, xq0, acc2[0][0]);
                acc2[0][1] = fma2(ad0, xq1, acc2[0][1]);
                acc2[1][0] = fma2(ad1, xq0, acc2[1][0]);
                acc2[1][1] = fma2(ad1, xq1, acc2[1][1]);
                acc2[2][0] = fma2(ad2, xq0, acc2[2][0]);
                acc2[2][1] = fma2(ad2, xq1, acc2[2][1]);
                acc2[3][0] = fma2(ad3, xq0, acc2[3][0]);
                acc2[3][1] = fma2(ad3, xq1, acc2[3][1]);
            }
            __syncthreads();
        }

        float* P = g_part + ((size_t)ns * BB + b) * KK * CC;
#pragma unroll
        for (int i = 0; i < 4; i++) {
            const float2 v0 = unpack2(acc2[i][0]);
            const float2 v1 = unpack2(acc2[i][1]);
            float4 o4 = make_float4(v0.x, v0.y, v1.x, v1.y);
            *reinterpret_cast<float4*>(&P[(size_t)(tk * 4 + i) * CC + c0 + tc * 4]) = o4;
        }
    }
    grid_bar();

    // ========== Phase D: epilogue, 2 (b,k) rows per block ==========
    {
        float* redw = (float*)SMEM;       // 2
        float* red = redw + 2;            // 2*4
        float* rfs = red + 8;             // 2
        const int h = tid >> 7;           // half 0/1
        const int ht = tid & 127;
        const int r = blk * 2 + h;        // 0..255
        const int b = r >> 6, k = r & 63;

        // issue all independent loads first
        float wv = 0.f;
        if (ht < 32) wv = g_wpart[(b * 32 + ht) * KK + k];
        const int c = ht * 4;
        const size_t base = (size_t)b * KK * CC + (size_t)k * CC + c;
        float4 p0 = *reinterpret_cast<const float4*>(&g_part[0 * BB * KK * CC + base]);
        float4 p1 = *reinterpret_cast<const float4*>(&g_part[1 * BB * KK * CC + base]);
        float4 p2 = *reinterpret_cast<const float4*>(&g_part[2 * BB * KK * CC + base]);
        float4 p3 = *reinterpret_cast<const float4*>(&g_part[3 * BB * KK * CC + base]);
        const float4 a = *reinterpret_cast<const float4*>(&anchor[k * CC + c]);
        const float4 iv = *reinterpret_cast<const float4*>(&g_inv[k * CC + c]);

        if (ht < 32) {
#pragma unroll
            for (int o = 16; o > 0; o >>= 1) wv += __shfl_xor_sync(0xffffffffu, wv, o);
            if (ht == 0) redw[h] = wv;
        }
        __syncthreads();
        const float w = redw[h];
        const float invden = 1.f / (w + 1e-7f);

        float4 s;
        s.x = (p0.x + p1.x) + (p2.x + p3.x);
        s.y = (p0.y + p1.y) + (p2.y + p3.y);
        s.z = (p0.z + p1.z) + (p2.z + p3.z);
        s.w = (p0.w + p1.w) + (p2.w + p3.w);
        float4 v;
        v.x = (s.x - w * a.x) * iv.x * invden;
        v.y = (s.y - w * a.y) * iv.y * invden;
        v.z = (s.z - w * a.z) * iv.z * invden;
        v.w = (s.w - w * a.w) * iv.w * invden;

        float ss = v.x * v.x + v.y * v.y + v.z * v.z + v.w * v.w;
#pragma unroll
        for (int o = 16; o > 0; o >>= 1) ss += __shfl_xor_sync(0xffffffffu, ss, o);
        if ((ht & 31) == 0) red[h * 4 + (ht >> 5)] = ss;
        __syncthreads();
        if (ht == 0) {
            const float sumsq = red[h * 4] + red[h * 4 + 1] + red[h * 4 + 2] + red[h * 4 + 3];
            rfs[h] = 0.125f / fmaxf(sqrtf(sumsq), 1e-12f);  // row norm * 1/sqrt(K)
        }
        __syncthreads();
        const float rf = rfs[h];
        float4 o4;
        o4.x = v.x * rf; o4.y = v.y * rf; o4.z = v.z * rf; o4.w = v.w * rf;
        *reinterpret_cast<float4*>(&nodes_out[((size_t)b * KK + k) * CC + c]) = o4;
    }
}

// ------------------------------------------------------------------
extern "C" void kernel_launch(void* const* d_in, const int* in_sizes, int n_in,
                              void* d_out, int out_size) {
    (void)in_sizes; (void)n_in; (void)out_size;
    const float* x = (const float*)d_in[0];       // (4,512,32,32)
    const float* anchor = (const float*)d_in[1];  // (64,512)
    const float* sp = (const float*)d_in[2];      // (64,512)
    float* out = (float*)d_out;
    float* nodes_out = out;                        // B*K*C (viewed (B,C,K))
    float* soft_out = out + (size_t)BB * KK * CC;  // B*K*N

    fused_all<<<GRID, 256>>>(x, anchor, sp, nodes_out, soft_out);
}